// round 6
// baseline (speedup 1.0000x reference)
#include <cuda_runtime.h>

// NURBS surface eval: DEG=3, N_CP=32x32, N_EVAL=2,000,000.
// Clamped-uniform knots: knot(i) = clamp(i-3,0,29)/29, span = floor(u*29)+3.
// Output: d_out[0..4N) = points (x,y,z,1); d_out[4N..8N) = normals (nx,ny,nz,0).
//
// R6: issue-bound -> cut instruction count with Blackwell f32x2 packed math:
//  * u-basis and v-basis Cox-de Boor computed together, one packed lane-pair.
//  * (x,y) packed in the tensor contraction; z scalar.
//  * rcp.approx.f32 (idle MUFU pipe) replaces integer-select reciprocal chains.
// Keeps R5's 8x bank-column-replicated smem table (zero LDS conflicts) and
// persistent 148x1024 launch.

#define NCP 32
#define NTHREADS 1024
#define NBLOCKS 148
#define TAB_BYTES (NCP * NCP * 8 * 16)   // 128 KB

typedef unsigned long long f2;   // packed (lo: u-lane / x, hi: v-lane / y)

__device__ __forceinline__ f2 pack2(float lo, float hi) {
    f2 r;
    asm("mov.b64 %0, {%1, %2};" : "=l"(r)
        : "r"(__float_as_uint(lo)), "r"(__float_as_uint(hi)));
    return r;
}
__device__ __forceinline__ void unpack2(f2 x, float& lo, float& hi) {
    unsigned a, b;
    asm("mov.b64 {%0, %1}, %2;" : "=r"(a), "=r"(b) : "l"(x));
    lo = __uint_as_float(a); hi = __uint_as_float(b);
}
__device__ __forceinline__ f2 add2(f2 a, f2 b) {
    f2 r; asm("add.rn.f32x2 %0, %1, %2;" : "=l"(r) : "l"(a), "l"(b)); return r;
}
__device__ __forceinline__ f2 mul2(f2 a, f2 b) {
    f2 r; asm("mul.rn.f32x2 %0, %1, %2;" : "=l"(r) : "l"(a), "l"(b)); return r;
}
__device__ __forceinline__ f2 fma2(f2 a, f2 b, f2 c) {
    f2 r; asm("fma.rn.f32x2 %0, %1, %2, %3;" : "=l"(r) : "l"(a), "l"(b), "l"(c)); return r;
}
__device__ __forceinline__ f2 neg2(f2 a) { return a ^ 0x8000000080000000ull; }
__device__ __forceinline__ f2 bc2(float x) { return pack2(x, x); }
__device__ __forceinline__ float rcpa(float x) {
    float r; asm("rcp.approx.f32 %0, %1;" : "=f"(r) : "f"(x)); return r;
}
__device__ __forceinline__ f2 rcp2(f2 x) {
    float a, b; unpack2(x, a, b);
    return pack2(rcpa(a), rcpa(b));
}

// Packed Cox-de Boor p=3 for BOTH parameter directions at once.
// lo lane = u-direction (span se), hi lane = v-direction (span sn).
// Nb2[r] = basis values, Db2[r] = first derivatives (already *3).
__device__ __forceinline__ void basis2(float u, float v, int se, int sn,
                                       f2* __restrict__ Nb2, f2* __restrict__ Db2)
{
    const float C = 1.0f / 29.0f;
    float sef = (float)se, snf = (float)sn;

    // Clamped knots around the span. nk2[t] = -knot (t=0..2, for "left"),
    // kp2[t] = +knot (t=0..2 <-> global t+3, for "right"). Negation folded in.
    f2 nk2[3], kp2[3];
#pragma unroll
    for (int t = 0; t < 3; ++t) {
        float au = fmaxf(fminf(fmaf(sef, -C, (float)(2 - t) * C), 0.0f), -1.0f);
        float av = fmaxf(fminf(fmaf(snf, -C, (float)(2 - t) * C), 0.0f), -1.0f);
        nk2[t] = pack2(au, av);
    }
#pragma unroll
    for (int t = 0; t < 3; ++t) {
        float au = fminf(fmaxf(fmaf(sef, C, (float)(t + 1) * C), 0.0f), 1.0f);
        float av = fminf(fmaxf(fmaf(snf, C, (float)(t + 1) * C), 0.0f), 1.0f);
        kp2[t] = pack2(au, av);
    }

    f2 u2  = pack2(u, v);
    f2 un2 = neg2(u2);

    f2 left2[4], right2[4];
#pragma unroll
    for (int j = 1; j <= 3; ++j) {
        left2[j]  = add2(u2, nk2[3 - j]);       // u - knot(span+1-j)
        right2[j] = add2(kp2[j - 1], un2);      // knot(span+j) - u
    }

    const f2 ONE2 = 0x3F8000003F800000ull;
    f2 colA[4];                 // column j-1 of ndu
    colA[0] = ONE2;
    f2 t3[3];                   // j=3 quotients == derivative t_r values
#pragma unroll
    for (int j = 1; j <= 3; ++j) {
        f2 colB[4];
        f2 saved = 0ull;
#pragma unroll
        for (int r = 0; r < j; ++r) {
            f2 den = add2(right2[r + 1], left2[j - r]);
            f2 tmp = mul2(colA[r], rcp2(den));
            if (j == 3) t3[r] = tmp;
            colB[r] = fma2(right2[r + 1], tmp, saved);
            saved = mul2(left2[j - r], tmp);
        }
        colB[j] = saved;
#pragma unroll
        for (int r = 0; r <= j; ++r) colA[r] = colB[r];
    }
    Nb2[0] = colA[0]; Nb2[1] = colA[1]; Nb2[2] = colA[2]; Nb2[3] = colA[3];

    const f2 P3 = 0x4040000040400000ull;   // (+3, +3)
    const f2 N3 = 0xC0400000C0400000ull;   // (-3, -3)
    Db2[0] = mul2(t3[0], N3);
    Db2[1] = mul2(add2(t3[0], neg2(t3[1])), P3);
    Db2[2] = mul2(add2(t3[1], neg2(t3[2])), P3);
    Db2[3] = mul2(t3[2], P3);
}

extern "C" __global__ void __launch_bounds__(NTHREADS, 1)
nurbs_surface_kernel(const float2* __restrict__ ep,
                     const float*  __restrict__ cp,
                     float4* __restrict__ out,
                     int n)
{
    extern __shared__ float4 tab[];   // [1024 cells][8 bank-columns]
    const int tid   = threadIdx.x;
    const int lane8 = tid & 7;

#pragma unroll
    for (int i = 0; i < 8; ++i) {
        int e = i * NTHREADS + tid;
        int cell = e >> 3;
        tab[e] = make_float4(cp[3 * cell + 0], cp[3 * cell + 1], cp[3 * cell + 2], 1.0f);
    }
    __syncthreads();

    float4* __restrict__ outn = out + n;

    for (int idx = blockIdx.x * NTHREADS + tid; idx < n; idx += NBLOCKS * NTHREADS) {
        float2 uv = ep[idx];

        int se = (int)floorf(uv.x * 29.0f);
        se = se < 0 ? 0 : (se > 28 ? 28 : se);
        int sn = (int)floorf(uv.y * 29.0f);
        sn = sn < 0 ? 0 : (sn > 28 ? 28 : sn);

        f2 Nb2[4], Db2[4];
        basis2(uv.x, uv.y, se, sn, Nb2, Db2);

        float Nu[4], Nv[4], Du[4], Dv[4];
#pragma unroll
        for (int i = 0; i < 4; ++i) {
            unpack2(Nb2[i], Nu[i], Nv[i]);
            unpack2(Db2[i], Du[i], Dv[i]);
        }
        f2 Nv2[4], Dv2[4];
#pragma unroll
        for (int s = 0; s < 4; ++s) { Nv2[s] = bc2(Nv[s]); Dv2[s] = bc2(Dv[s]); }

        // Conflict-free gather base: this lane's private bank column.
        const float4* __restrict__ p = tab + ((se * NCP + sn) * 8 + lane8);

        f2 pxy = 0ull, exy = 0ull, fxy = 0ull;     // packed (x,y) accumulators
        float pz = 0.f, ez = 0.f, fz = 0.f;
#pragma unroll
        for (int r = 0; r < 4; ++r) {
            f2 axy = 0ull, bxy = 0ull;
            float az = 0.f, bz = 0.f;
#pragma unroll
            for (int s = 0; s < 4; ++s) {
                float4 g = p[(r * NCP + s) * 8];
                f2 gxy = pack2(g.x, g.y);
                axy = fma2(Nv2[s], gxy, axy);
                az  = fmaf(Nv[s], g.z, az);
                bxy = fma2(Dv2[s], gxy, bxy);
                bz  = fmaf(Dv[s], g.z, bz);
            }
            f2 nu2 = bc2(Nu[r]), du2 = bc2(Du[r]);
            pxy = fma2(nu2, axy, pxy);
            exy = fma2(du2, axy, exy);
            fxy = fma2(nu2, bxy, fxy);
            pz = fmaf(Nu[r], az, pz);
            ez = fmaf(Du[r], az, ez);
            fz = fmaf(Nu[r], bz, fz);
        }

        float px, py, ex, ey, fx, fy;
        unpack2(pxy, px, py);
        unpack2(exy, ex, ey);
        unpack2(fxy, fx, fy);

        // normal = normalize(cross(d_e, d_n))
        float cx = ey * fz - ez * fy;
        float cy = ez * fx - ex * fz;
        float cz = ex * fy - ey * fx;
        float il = rsqrtf(cx * cx + cy * cy + cz * cz);

        out[idx]  = make_float4(px, py, pz, 1.0f);
        outn[idx] = make_float4(cx * il, cy * il, cz * il, 0.0f);
    }
}

extern "C" void kernel_launch(void* const* d_in, const int* in_sizes, int n_in,
                              void* d_out, int out_size)
{
    const float2* ep = (const float2*)d_in[0];   // evaluation_points (N,2)
    const float*  cp = (const float*)d_in[1];    // control_points (32,32,3)
    int n = in_sizes[0] / 2;
    float4* out = (float4*)d_out;

    cudaFuncSetAttribute(nurbs_surface_kernel,
                         cudaFuncAttributeMaxDynamicSharedMemorySize, TAB_BYTES);

    nurbs_surface_kernel<<<NBLOCKS, NTHREADS, TAB_BYTES>>>(ep, cp, out, n);
}